// round 6
// baseline (speedup 1.0000x reference)
#include <cuda_runtime.h>
#include <math.h>
#include <stdint.h>

#define BSZ   8
#define SEQ   19947
#define MROWS 159576          // BSZ*SEQ
#define CH    256
#define NC    91
#define NTOP  20

// output layout (float32, concatenated flattened tuple)
#define OFF_OUT  0            // (8,20,95)
#define OFF_REF  15200        // (8,20,4)
#define OFF_KEEP 15840        // (8,20)
#define OFF_SC   16000        // (8,20)

// ---------------- scratch (device globals: allocation-free) ----------------
__device__ float g_tmp[MROWS * CH];      // G1 out (pre-LN), later h2
__device__ float g_outmem[MROWS * CH];
__device__ float g_h1[MROWS * CH];
__device__ float g_logits[MROWS * NC];
__device__ float g_scores[MROWS];
__device__ float g_scratch[MROWS];
__device__ float g_prop[MROWS * 4];
__device__ float g_coords[MROWS * 4];
__device__ unsigned char g_rowinv[MROWS];
__device__ int   g_topidx[BSZ * NTOP];
__device__ float g_topsc[BSZ * NTOP];

// ---------------- kernel 0: proposal logits + row invalid flags ------------
__global__ void props_kernel(const unsigned char* __restrict__ mask,
                             unsigned char* __restrict__ rowInv,
                             float* __restrict__ prop)
{
    int row = blockIdx.x * blockDim.x + threadIdx.x;
    if (row >= MROWS) return;
    int s = row % SEQ;
    int Hh, Ww, lvl, t;
    if (s < 15000)      { lvl = 0; Hh = 100; Ww = 150; t = s; }
    else if (s < 18750) { lvl = 1; Hh = 50;  Ww = 75;  t = s - 15000; }
    else if (s < 19700) { lvl = 2; Hh = 25;  Ww = 38;  t = s - 18750; }
    else                { lvl = 3; Hh = 13;  Ww = 19;  t = s - 19700; }
    int y = t / Ww, x = t % Ww;
    float cx = ((float)x + 0.5f) / (float)Ww;
    float cy = ((float)y + 0.5f) / (float)Hh;
    float wh = 0.05f * (float)(1 << lvl);
    bool valid = (cx > 0.01f) && (cx < 0.99f) &&
                 (cy > 0.01f) && (cy < 0.99f) &&
                 (wh > 0.01f) && (wh < 0.99f);
    bool inv = (mask[row] != 0) || !valid;
    rowInv[row] = inv ? 1 : 0;
    if (inv) {
        prop[row*4+0] = INFINITY; prop[row*4+1] = INFINITY;
        prop[row*4+2] = INFINITY; prop[row*4+3] = INFINITY;
    } else {
        float lw = logf(wh / (1.f - wh));
        prop[row*4+0] = logf(cx / (1.f - cx));
        prop[row*4+1] = logf(cy / (1.f - cy));
        prop[row*4+2] = lw;
        prop[row*4+3] = lw;
    }
}

// ---------------- SGEMM: C = act(A[M,256] @ B[256,N] + bias) ---------------
__device__ __forceinline__ float4 loadA4(const float* __restrict__ A, int gr, int kOff,
                                         int M, const unsigned char* __restrict__ rowInv)
{
    if (gr < M && (rowInv == nullptr || rowInv[gr] == 0))
        return *reinterpret_cast<const float4*>(A + (size_t)gr * CH + kOff);
    return make_float4(0.f, 0.f, 0.f, 0.f);
}
__device__ __forceinline__ float4 loadB4(const float* __restrict__ Bm, int k, int gc, int N)
{
    if ((N & 3) == 0)  // N=256 path: always in-bounds & 16B aligned
        return *reinterpret_cast<const float4*>(Bm + (size_t)k * N + gc);
    float4 v;
    v.x = (gc + 0 < N) ? Bm[(size_t)k * N + gc + 0] : 0.f;
    v.y = (gc + 1 < N) ? Bm[(size_t)k * N + gc + 1] : 0.f;
    v.z = (gc + 2 < N) ? Bm[(size_t)k * N + gc + 2] : 0.f;
    v.w = (gc + 3 < N) ? Bm[(size_t)k * N + gc + 3] : 0.f;
    return v;
}

__global__ void __launch_bounds__(256)
sgemm_kernel(const float* __restrict__ A, const float* __restrict__ Bm,
             const float* __restrict__ bias, float* __restrict__ C,
             int M, int N, int act, const unsigned char* __restrict__ rowInv)
{
    __shared__ float As[2][16][128 + 4];
    __shared__ float Bs[2][16][64];

    const int tid = threadIdx.x;
    const int rowBase = blockIdx.x * 128;
    const int colBase = blockIdx.y * 64;

    const int warp = tid >> 5, lane = tid & 31;
    const int tRow = (warp & 3) * 32 + (lane & 3) * 8;   // 8 rows
    const int tCol = (warp >> 2) * 32 + (lane >> 2) * 4; // 4 cols

    const int aRow0 = tid >> 2,          aK0 = (tid & 3) << 2;
    const int aRow1 = (tid + 256) >> 2,  aK1 = (tid & 3) << 2; // (tid+256)&3 == tid&3
    const int bK = tid >> 4, bN = (tid & 15) << 2;

    float acc[8][4];
#pragma unroll
    for (int r = 0; r < 8; r++)
#pragma unroll
        for (int c = 0; c < 4; c++) acc[r][c] = 0.f;

    float4 a0r = loadA4(A, rowBase + aRow0, aK0, M, rowInv);
    float4 a1r = loadA4(A, rowBase + aRow1, aK1, M, rowInv);
    float4 b0r = loadB4(Bm, bK, colBase + bN, N);
    As[0][aK0+0][aRow0] = a0r.x; As[0][aK0+1][aRow0] = a0r.y;
    As[0][aK0+2][aRow0] = a0r.z; As[0][aK0+3][aRow0] = a0r.w;
    As[0][aK1+0][aRow1] = a1r.x; As[0][aK1+1][aRow1] = a1r.y;
    As[0][aK1+2][aRow1] = a1r.z; As[0][aK1+3][aRow1] = a1r.w;
    *reinterpret_cast<float4*>(&Bs[0][bK][bN]) = b0r;
    __syncthreads();

#pragma unroll 1
    for (int kb = 0; kb < 16; kb++) {
        const int cur = kb & 1;
        if (kb < 15) {
            a0r = loadA4(A, rowBase + aRow0, (kb + 1) * 16 + aK0, M, rowInv);
            a1r = loadA4(A, rowBase + aRow1, (kb + 1) * 16 + aK1, M, rowInv);
            b0r = loadB4(Bm, (kb + 1) * 16 + bK, colBase + bN, N);
        }
#pragma unroll
        for (int kk = 0; kk < 16; kk++) {
            float4 a0 = *reinterpret_cast<const float4*>(&As[cur][kk][tRow]);
            float4 a1 = *reinterpret_cast<const float4*>(&As[cur][kk][tRow + 4]);
            float4 b  = *reinterpret_cast<const float4*>(&Bs[cur][kk][tCol]);
            float av[8] = {a0.x, a0.y, a0.z, a0.w, a1.x, a1.y, a1.z, a1.w};
            float bv[4] = {b.x, b.y, b.z, b.w};
#pragma unroll
            for (int r = 0; r < 8; r++)
#pragma unroll
                for (int c = 0; c < 4; c++)
                    acc[r][c] = fmaf(av[r], bv[c], acc[r][c]);
        }
        if (kb < 15) {
            const int nxt = 1 - cur;
            As[nxt][aK0+0][aRow0] = a0r.x; As[nxt][aK0+1][aRow0] = a0r.y;
            As[nxt][aK0+2][aRow0] = a0r.z; As[nxt][aK0+3][aRow0] = a0r.w;
            As[nxt][aK1+0][aRow1] = a1r.x; As[nxt][aK1+1][aRow1] = a1r.y;
            As[nxt][aK1+2][aRow1] = a1r.z; As[nxt][aK1+3][aRow1] = a1r.w;
            *reinterpret_cast<float4*>(&Bs[nxt][bK][bN]) = b0r;
            __syncthreads();
        }
    }

#pragma unroll
    for (int r = 0; r < 8; r++) {
        int gr = rowBase + tRow + r;
        if (gr >= M) continue;
#pragma unroll
        for (int c = 0; c < 4; c++) {
            int gc = colBase + tCol + c;
            if (gc >= N) continue;
            float v = acc[r][c] + bias[gc];
            if (act) v = fmaxf(v, 0.f);
            C[(size_t)gr * N + gc] = v;
        }
    }
}

// ---------------- LayerNorm (warp per row) ----------------------------------
__global__ void ln_kernel(const float* __restrict__ X, const float* __restrict__ g,
                          const float* __restrict__ b, float* __restrict__ Y)
{
    int row = (blockIdx.x * blockDim.x + threadIdx.x) >> 5;
    if (row >= MROWS) return;
    int lane = threadIdx.x & 31;
    const float* x = X + (size_t)row * CH + lane * 8;
    float4 v0 = *reinterpret_cast<const float4*>(x);
    float4 v1 = *reinterpret_cast<const float4*>(x + 4);
    float s = v0.x+v0.y+v0.z+v0.w + v1.x+v1.y+v1.z+v1.w;
#pragma unroll
    for (int off = 16; off; off >>= 1) s += __shfl_xor_sync(0xffffffffu, s, off);
    float mean = s * (1.f / 256.f);
    float d0 = v0.x-mean, d1 = v0.y-mean, d2 = v0.z-mean, d3 = v0.w-mean;
    float d4 = v1.x-mean, d5 = v1.y-mean, d6 = v1.z-mean, d7 = v1.w-mean;
    float q = d0*d0+d1*d1+d2*d2+d3*d3+d4*d4+d5*d5+d6*d6+d7*d7;
#pragma unroll
    for (int off = 16; off; off >>= 1) q += __shfl_xor_sync(0xffffffffu, q, off);
    float var = q * (1.f / 256.f);
    float inv = 1.f / sqrtf(var + 1e-5f);
    float4 gg0 = *reinterpret_cast<const float4*>(g + lane * 8);
    float4 gg1 = *reinterpret_cast<const float4*>(g + lane * 8 + 4);
    float4 bb0 = *reinterpret_cast<const float4*>(b + lane * 8);
    float4 bb1 = *reinterpret_cast<const float4*>(b + lane * 8 + 4);
    float4 o0, o1;
    o0.x = d0*inv*gg0.x + bb0.x; o0.y = d1*inv*gg0.y + bb0.y;
    o0.z = d2*inv*gg0.z + bb0.z; o0.w = d3*inv*gg0.w + bb0.w;
    o1.x = d4*inv*gg1.x + bb1.x; o1.y = d5*inv*gg1.y + bb1.y;
    o1.z = d6*inv*gg1.z + bb1.z; o1.w = d7*inv*gg1.w + bb1.w;
    float* y = Y + (size_t)row * CH + lane * 8;
    *reinterpret_cast<float4*>(y) = o0;
    *reinterpret_cast<float4*>(y + 4) = o1;
}

// ---------------- row-max of logits (warp per row) --------------------------
__global__ void rowmax_kernel(const float* __restrict__ logits, float* __restrict__ scores)
{
    int row = (blockIdx.x * blockDim.x + threadIdx.x) >> 5;
    if (row >= MROWS) return;
    int lane = threadIdx.x & 31;
    float m = -INFINITY;
    for (int c = lane; c < NC; c += 32) m = fmaxf(m, logits[(size_t)row * NC + c]);
#pragma unroll
    for (int off = 16; off; off >>= 1) m = fmaxf(m, __shfl_xor_sync(0xffffffffu, m, off));
    if (lane == 0) scores[row] = m;
}

// ---------------- coords = h2 @ W3 + b3 + prop (warp per row) ---------------
__global__ void coords_kernel(const float* __restrict__ H2, const float* __restrict__ W3,
                              const float* __restrict__ b3, const float* __restrict__ prop,
                              float* __restrict__ out)
{
    int row = (blockIdx.x * blockDim.x + threadIdx.x) >> 5;
    if (row >= MROWS) return;
    int lane = threadIdx.x & 31;
    const float* h = H2 + (size_t)row * CH;
    float4 acc = make_float4(0.f, 0.f, 0.f, 0.f);
    for (int k = lane; k < CH; k += 32) {
        float a = h[k];
        float4 w = *reinterpret_cast<const float4*>(W3 + k * 4);
        acc.x = fmaf(a, w.x, acc.x); acc.y = fmaf(a, w.y, acc.y);
        acc.z = fmaf(a, w.z, acc.z); acc.w = fmaf(a, w.w, acc.w);
    }
#pragma unroll
    for (int off = 16; off; off >>= 1) {
        acc.x += __shfl_xor_sync(0xffffffffu, acc.x, off);
        acc.y += __shfl_xor_sync(0xffffffffu, acc.y, off);
        acc.z += __shfl_xor_sync(0xffffffffu, acc.z, off);
        acc.w += __shfl_xor_sync(0xffffffffu, acc.w, off);
    }
    if (lane == 0) {
        out[row*4+0] = acc.x + b3[0] + prop[row*4+0];
        out[row*4+1] = acc.y + b3[1] + prop[row*4+1];
        out[row*4+2] = acc.z + b3[2] + prop[row*4+2];
        out[row*4+3] = acc.w + b3[3] + prop[row*4+3];
    }
}

// ---------------- top-20 per batch (block per batch) -------------------------
__global__ void topk_kernel(const float* __restrict__ scores, float* __restrict__ scratch,
                            int* __restrict__ topIdx, float* __restrict__ topSc)
{
    int b = blockIdx.x, tid = threadIdx.x;
    const float* s = scores + b * SEQ;
    float* t = scratch + b * SEQ;
    for (int i = tid; i < SEQ; i += blockDim.x) t[i] = s[i];
    __syncthreads();
    __shared__ float rv[1024];
    __shared__ int   ri[1024];
    for (int it = 0; it < NTOP; it++) {
        float bv = -INFINITY; int bi = 0x7fffffff;
        for (int i = tid; i < SEQ; i += blockDim.x) {
            float v = t[i];
            if (v > bv) { bv = v; bi = i; }
        }
        rv[tid] = bv; ri[tid] = bi;
        __syncthreads();
        for (int off = 512; off > 0; off >>= 1) {
            if (tid < off) {
                float ov = rv[tid + off]; int oi = ri[tid + off];
                if (ov > rv[tid] || (ov == rv[tid] && oi < ri[tid])) { rv[tid] = ov; ri[tid] = oi; }
            }
            __syncthreads();
        }
        if (tid == 0) {
            topIdx[b * NTOP + it] = ri[0];
            topSc[b * NTOP + it]  = rv[0];
            t[ri[0]] = -INFINITY;
        }
        __syncthreads();
    }
}

// ---------------- final: gather + sigmoid + boxes + NMS ----------------------
__global__ void final_kernel(const float* __restrict__ logits, const float* __restrict__ coords,
                             const int* __restrict__ topIdx, const float* __restrict__ topSc,
                             const float* __restrict__ WH, float* __restrict__ out)
{
    int b = blockIdx.x, tid = threadIdx.x;
    __shared__ int   idxs[NTOP];
    __shared__ float refp[NTOP][4];
    __shared__ float boxes[NTOP][4];
    if (tid < NTOP) idxs[tid] = topIdx[b * NTOP + tid];
    __syncthreads();

    for (int o = tid; o < NTOP * NC; o += blockDim.x) {
        int k = o / NC, c = o % NC;
        size_t row = (size_t)b * SEQ + idxs[k];
        out[OFF_OUT + b * (NTOP * (NC + 4)) + k * (NC + 4) + c] = logits[row * NC + c];
    }
    if (tid < NTOP * 4) {
        int k = tid >> 2, c = tid & 3;
        size_t row = (size_t)b * SEQ + idxs[k];
        float v = coords[row * 4 + c];
        out[OFF_OUT + b * (NTOP * (NC + 4)) + k * (NC + 4) + NC + c] = v;
        float r = 1.f / (1.f + expf(-v));
        out[OFF_REF + b * (NTOP * 4) + k * 4 + c] = r;
        refp[k][c] = r;
    }
    if (tid < NTOP) out[OFF_SC + b * NTOP + tid] = topSc[b * NTOP + tid];
    __syncthreads();
    if (tid < NTOP) {
        float cx = refp[tid][0], cy = refp[tid][1], w = refp[tid][2], h = refp[tid][3];
        boxes[tid][0] = truncf((cx - 0.5f * w) * WH[b * 4 + 0]);
        boxes[tid][1] = truncf((cy - 0.5f * h) * WH[b * 4 + 1]);
        boxes[tid][2] = truncf((cx + 0.5f * w) * WH[b * 4 + 2]);
        boxes[tid][3] = truncf((cy + 0.5f * h) * WH[b * 4 + 3]);
    }
    __syncthreads();
    if (tid == 0) {
        bool supp[NTOP];
        float area[NTOP];
        for (int k = 0; k < NTOP; k++) {
            supp[k] = false;
            area[k] = (boxes[k][2] - boxes[k][0]) * (boxes[k][3] - boxes[k][1]);
        }
        for (int i = 0; i < NTOP; i++) {
            if (supp[i]) continue;
            for (int j = i + 1; j < NTOP; j++) {
                float xx1 = fmaxf(boxes[i][0], boxes[j][0]);
                float yy1 = fmaxf(boxes[i][1], boxes[j][1]);
                float xx2 = fminf(boxes[i][2], boxes[j][2]);
                float yy2 = fminf(boxes[i][3], boxes[j][3]);
                float inter = fmaxf(xx2 - xx1, 0.f) * fmaxf(yy2 - yy1, 0.f);
                float iou = inter / (area[i] + area[j] - inter);
                if (iou > 0.5f) supp[j] = true;
            }
        }
        for (int k = 0; k < NTOP; k++)
            out[OFF_KEEP + b * NTOP + k] = supp[k] ? 0.f : 1.f;
    }
}

// ---------------- launch -----------------------------------------------------
extern "C" void kernel_launch(void* const* d_in, const int* in_sizes, int n_in,
                              void* d_out, int out_size)
{
    const float* memory        = (const float*)d_in[0];
    const unsigned char* mask  = (const unsigned char*)d_in[1];
    const float* WH            = (const float*)d_in[2];
    const float* W_enc         = (const float*)d_in[3];
    const float* b_enc         = (const float*)d_in[4];
    const float* ln_g          = (const float*)d_in[5];
    const float* ln_b          = (const float*)d_in[6];
    const float* W_cls         = (const float*)d_in[7];
    const float* b_cls         = (const float*)d_in[8];
    const float* W1            = (const float*)d_in[9];
    const float* b1            = (const float*)d_in[10];
    const float* W2            = (const float*)d_in[11];
    const float* b2            = (const float*)d_in[12];
    const float* W3            = (const float*)d_in[13];
    const float* b3            = (const float*)d_in[14];
    float* out = (float*)d_out;

    float *p_tmp, *p_outmem, *p_h1, *p_logits, *p_scores, *p_scratch, *p_prop, *p_coords, *p_topsc;
    unsigned char* p_rowinv; int* p_topidx;
    cudaGetSymbolAddress((void**)&p_tmp,     g_tmp);
    cudaGetSymbolAddress((void**)&p_outmem,  g_outmem);
    cudaGetSymbolAddress((void**)&p_h1,      g_h1);
    cudaGetSymbolAddress((void**)&p_logits,  g_logits);
    cudaGetSymbolAddress((void**)&p_scores,  g_scores);
    cudaGetSymbolAddress((void**)&p_scratch, g_scratch);
    cudaGetSymbolAddress((void**)&p_prop,    g_prop);
    cudaGetSymbolAddress((void**)&p_coords,  g_coords);
    cudaGetSymbolAddress((void**)&p_rowinv,  g_rowinv);
    cudaGetSymbolAddress((void**)&p_topidx,  g_topidx);
    cudaGetSymbolAddress((void**)&p_topsc,   g_topsc);

    props_kernel<<<(MROWS + 255) / 256, 256>>>(mask, p_rowinv, p_prop);

    dim3 gFull((MROWS + 127) / 128, 4);
    dim3 gCls((MROWS + 127) / 128, 2);
    // tmp = mem_masked @ W_enc + b_enc
    sgemm_kernel<<<gFull, 256>>>(memory, W_enc, b_enc, p_tmp, MROWS, CH, 0, p_rowinv);
    // out_mem = LN(tmp)*g + b
    ln_kernel<<<MROWS / 8, 256>>>(p_tmp, ln_g, ln_b, p_outmem);
    // h1 = relu(out_mem @ W1 + b1)
    sgemm_kernel<<<gFull, 256>>>(p_outmem, W1, b1, p_h1, MROWS, CH, 1, nullptr);
    // h2 = relu(h1 @ W2 + b2)  (reuse tmp)
    sgemm_kernel<<<gFull, 256>>>(p_h1, W2, b2, p_tmp, MROWS, CH, 1, nullptr);
    // logits = out_mem @ W_cls + b_cls
    sgemm_kernel<<<gCls, 256>>>(p_outmem, W_cls, b_cls, p_logits, MROWS, NC, 0, nullptr);
    // scores = rowmax(logits)
    rowmax_kernel<<<SEQ, 256>>>(p_logits, p_scores);
    // coords = h2 @ W3 + b3 + prop
    coords_kernel<<<SEQ, 256>>>(p_tmp, W3, b3, p_prop, p_coords);
    // top-20 per batch
    topk_kernel<<<BSZ, 1024>>>(p_scores, p_scratch, p_topidx, p_topsc);
    // gather + sigmoid + NMS + writes
    final_kernel<<<BSZ, 128>>>(p_logits, p_coords, p_topidx, p_topsc, WH, out);

    (void)in_sizes; (void)n_in; (void)out_size;
}

// round 7
// speedup vs baseline: 1.3615x; 1.3615x over previous
#include <cuda_runtime.h>
#include <math.h>
#include <stdint.h>

#define BSZ   8
#define SEQ   19947
#define MROWS 159576          // BSZ*SEQ
#define CH    256
#define NC    91
#define NTOP  20

// output layout (float32, concatenated flattened tuple)
#define OFF_OUT  0            // (8,20,95)
#define OFF_REF  15200        // (8,20,4)
#define OFF_KEEP 15840        // (8,20)
#define OFF_SC   16000        // (8,20)

// ---------------- scratch (device globals: allocation-free) ----------------
__device__ float g_tmp[MROWS * CH];      // G1 out (pre-LN), later h2
__device__ float g_outmem[MROWS * CH];
__device__ float g_h1[MROWS * CH];
__device__ float g_logits[MROWS * NC];
__device__ float g_scores[MROWS];
__device__ float g_scratch[MROWS];
__device__ float g_prop[MROWS * 4];
__device__ float g_coords[MROWS * 4];
__device__ unsigned char g_rowinv[MROWS];
__device__ int   g_topidx[BSZ * NTOP];
__device__ float g_topsc[BSZ * NTOP];

// ---------------- kernel 0: proposal logits + row invalid flags ------------
__global__ void props_kernel(const unsigned char* __restrict__ mask,
                             unsigned char* __restrict__ rowInv,
                             float* __restrict__ prop)
{
    int row = blockIdx.x * blockDim.x + threadIdx.x;
    if (row >= MROWS) return;
    int s = row % SEQ;
    int Hh, Ww, lvl, t;
    if (s < 15000)      { lvl = 0; Hh = 100; Ww = 150; t = s; }
    else if (s < 18750) { lvl = 1; Hh = 50;  Ww = 75;  t = s - 15000; }
    else if (s < 19700) { lvl = 2; Hh = 25;  Ww = 38;  t = s - 18750; }
    else                { lvl = 3; Hh = 13;  Ww = 19;  t = s - 19700; }
    int y = t / Ww, x = t % Ww;
    float cx = ((float)x + 0.5f) / (float)Ww;
    float cy = ((float)y + 0.5f) / (float)Hh;
    float wh = 0.05f * (float)(1 << lvl);
    bool valid = (cx > 0.01f) && (cx < 0.99f) &&
                 (cy > 0.01f) && (cy < 0.99f) &&
                 (wh > 0.01f) && (wh < 0.99f);
    bool inv = (mask[row] != 0) || !valid;
    rowInv[row] = inv ? 1 : 0;
    if (inv) {
        prop[row*4+0] = INFINITY; prop[row*4+1] = INFINITY;
        prop[row*4+2] = INFINITY; prop[row*4+3] = INFINITY;
    } else {
        float lw = logf(wh / (1.f - wh));
        prop[row*4+0] = logf(cx / (1.f - cx));
        prop[row*4+1] = logf(cy / (1.f - cy));
        prop[row*4+2] = lw;
        prop[row*4+3] = lw;
    }
}

// ---------------- SGEMM: C = act(A[M,256] @ B[256,N] + bias) ---------------
__device__ __forceinline__ float4 loadA4(const float* __restrict__ A, int gr, int kOff,
                                         int M, const unsigned char* __restrict__ rowInv)
{
    if (gr < M && (rowInv == nullptr || rowInv[gr] == 0))
        return *reinterpret_cast<const float4*>(A + (size_t)gr * CH + kOff);
    return make_float4(0.f, 0.f, 0.f, 0.f);
}
__device__ __forceinline__ float4 loadB4(const float* __restrict__ Bm, int k, int gc, int N)
{
    if ((N & 3) == 0)  // N=256 path: always in-bounds & 16B aligned
        return *reinterpret_cast<const float4*>(Bm + (size_t)k * N + gc);
    float4 v;
    v.x = (gc + 0 < N) ? Bm[(size_t)k * N + gc + 0] : 0.f;
    v.y = (gc + 1 < N) ? Bm[(size_t)k * N + gc + 1] : 0.f;
    v.z = (gc + 2 < N) ? Bm[(size_t)k * N + gc + 2] : 0.f;
    v.w = (gc + 3 < N) ? Bm[(size_t)k * N + gc + 3] : 0.f;
    return v;
}

__global__ void __launch_bounds__(256)
sgemm_kernel(const float* __restrict__ A, const float* __restrict__ Bm,
             const float* __restrict__ bias, float* __restrict__ C,
             int M, int N, int act, const unsigned char* __restrict__ rowInv)
{
    __shared__ float As[2][16][128 + 4];
    __shared__ float Bs[2][16][64];

    const int tid = threadIdx.x;
    const int rowBase = blockIdx.x * 128;
    const int colBase = blockIdx.y * 64;

    const int warp = tid >> 5, lane = tid & 31;
    const int tRow = (warp & 3) * 32 + (lane & 3) * 8;   // 8 rows
    const int tCol = (warp >> 2) * 32 + (lane >> 2) * 4; // 4 cols

    const int aRow0 = tid >> 2,          aK0 = (tid & 3) << 2;
    const int aRow1 = (tid + 256) >> 2,  aK1 = (tid & 3) << 2; // (tid+256)&3 == tid&3
    const int bK = tid >> 4, bN = (tid & 15) << 2;

    float acc[8][4];
#pragma unroll
    for (int r = 0; r < 8; r++)
#pragma unroll
        for (int c = 0; c < 4; c++) acc[r][c] = 0.f;

    float4 a0r = loadA4(A, rowBase + aRow0, aK0, M, rowInv);
    float4 a1r = loadA4(A, rowBase + aRow1, aK1, M, rowInv);
    float4 b0r = loadB4(Bm, bK, colBase + bN, N);
    As[0][aK0+0][aRow0] = a0r.x; As[0][aK0+1][aRow0] = a0r.y;
    As[0][aK0+2][aRow0] = a0r.z; As[0][aK0+3][aRow0] = a0r.w;
    As[0][aK1+0][aRow1] = a1r.x; As[0][aK1+1][aRow1] = a1r.y;
    As[0][aK1+2][aRow1] = a1r.z; As[0][aK1+3][aRow1] = a1r.w;
    *reinterpret_cast<float4*>(&Bs[0][bK][bN]) = b0r;
    __syncthreads();

#pragma unroll 1
    for (int kb = 0; kb < 16; kb++) {
        const int cur = kb & 1;
        if (kb < 15) {
            a0r = loadA4(A, rowBase + aRow0, (kb + 1) * 16 + aK0, M, rowInv);
            a1r = loadA4(A, rowBase + aRow1, (kb + 1) * 16 + aK1, M, rowInv);
            b0r = loadB4(Bm, (kb + 1) * 16 + bK, colBase + bN, N);
        }
#pragma unroll
        for (int kk = 0; kk < 16; kk++) {
            float4 a0 = *reinterpret_cast<const float4*>(&As[cur][kk][tRow]);
            float4 a1 = *reinterpret_cast<const float4*>(&As[cur][kk][tRow + 4]);
            float4 b  = *reinterpret_cast<const float4*>(&Bs[cur][kk][tCol]);
            float av[8] = {a0.x, a0.y, a0.z, a0.w, a1.x, a1.y, a1.z, a1.w};
            float bv[4] = {b.x, b.y, b.z, b.w};
#pragma unroll
            for (int r = 0; r < 8; r++)
#pragma unroll
                for (int c = 0; c < 4; c++)
                    acc[r][c] = fmaf(av[r], bv[c], acc[r][c]);
        }
        if (kb < 15) {
            const int nxt = 1 - cur;
            As[nxt][aK0+0][aRow0] = a0r.x; As[nxt][aK0+1][aRow0] = a0r.y;
            As[nxt][aK0+2][aRow0] = a0r.z; As[nxt][aK0+3][aRow0] = a0r.w;
            As[nxt][aK1+0][aRow1] = a1r.x; As[nxt][aK1+1][aRow1] = a1r.y;
            As[nxt][aK1+2][aRow1] = a1r.z; As[nxt][aK1+3][aRow1] = a1r.w;
            *reinterpret_cast<float4*>(&Bs[nxt][bK][bN]) = b0r;
            __syncthreads();
        }
    }

#pragma unroll
    for (int r = 0; r < 8; r++) {
        int gr = rowBase + tRow + r;
        if (gr >= M) continue;
#pragma unroll
        for (int c = 0; c < 4; c++) {
            int gc = colBase + tCol + c;
            if (gc >= N) continue;
            float v = acc[r][c] + bias[gc];
            if (act) v = fmaxf(v, 0.f);
            C[(size_t)gr * N + gc] = v;
        }
    }
}

// ---------------- LayerNorm (warp per row) ----------------------------------
__global__ void ln_kernel(const float* __restrict__ X, const float* __restrict__ g,
                          const float* __restrict__ b, float* __restrict__ Y)
{
    int row = (blockIdx.x * blockDim.x + threadIdx.x) >> 5;
    if (row >= MROWS) return;
    int lane = threadIdx.x & 31;
    const float* x = X + (size_t)row * CH + lane * 8;
    float4 v0 = *reinterpret_cast<const float4*>(x);
    float4 v1 = *reinterpret_cast<const float4*>(x + 4);
    float s = v0.x+v0.y+v0.z+v0.w + v1.x+v1.y+v1.z+v1.w;
#pragma unroll
    for (int off = 16; off; off >>= 1) s += __shfl_xor_sync(0xffffffffu, s, off);
    float mean = s * (1.f / 256.f);
    float d0 = v0.x-mean, d1 = v0.y-mean, d2 = v0.z-mean, d3 = v0.w-mean;
    float d4 = v1.x-mean, d5 = v1.y-mean, d6 = v1.z-mean, d7 = v1.w-mean;
    float q = d0*d0+d1*d1+d2*d2+d3*d3+d4*d4+d5*d5+d6*d6+d7*d7;
#pragma unroll
    for (int off = 16; off; off >>= 1) q += __shfl_xor_sync(0xffffffffu, q, off);
    float var = q * (1.f / 256.f);
    float inv = 1.f / sqrtf(var + 1e-5f);
    float4 gg0 = *reinterpret_cast<const float4*>(g + lane * 8);
    float4 gg1 = *reinterpret_cast<const float4*>(g + lane * 8 + 4);
    float4 bb0 = *reinterpret_cast<const float4*>(b + lane * 8);
    float4 bb1 = *reinterpret_cast<const float4*>(b + lane * 8 + 4);
    float4 o0, o1;
    o0.x = d0*inv*gg0.x + bb0.x; o0.y = d1*inv*gg0.y + bb0.y;
    o0.z = d2*inv*gg0.z + bb0.z; o0.w = d3*inv*gg0.w + bb0.w;
    o1.x = d4*inv*gg1.x + bb1.x; o1.y = d5*inv*gg1.y + bb1.y;
    o1.z = d6*inv*gg1.z + bb1.z; o1.w = d7*inv*gg1.w + bb1.w;
    float* y = Y + (size_t)row * CH + lane * 8;
    *reinterpret_cast<float4*>(y) = o0;
    *reinterpret_cast<float4*>(y + 4) = o1;
}

// ---------------- row-max of logits (warp per row) --------------------------
__global__ void rowmax_kernel(const float* __restrict__ logits, float* __restrict__ scores)
{
    int row = (blockIdx.x * blockDim.x + threadIdx.x) >> 5;
    if (row >= MROWS) return;
    int lane = threadIdx.x & 31;
    float m = -INFINITY;
    for (int c = lane; c < NC; c += 32) m = fmaxf(m, logits[(size_t)row * NC + c]);
#pragma unroll
    for (int off = 16; off; off >>= 1) m = fmaxf(m, __shfl_xor_sync(0xffffffffu, m, off));
    if (lane == 0) scores[row] = m;
}

// ---------------- coords = h2 @ W3 + b3 + prop (warp per row) ---------------
__global__ void coords_kernel(const float* __restrict__ H2, const float* __restrict__ W3,
                              const float* __restrict__ b3, const float* __restrict__ prop,
                              float* __restrict__ out)
{
    int row = (blockIdx.x * blockDim.x + threadIdx.x) >> 5;
    if (row >= MROWS) return;
    int lane = threadIdx.x & 31;
    const float* h = H2 + (size_t)row * CH;
    float4 acc = make_float4(0.f, 0.f, 0.f, 0.f);
    for (int k = lane; k < CH; k += 32) {
        float a = h[k];
        float4 w = *reinterpret_cast<const float4*>(W3 + k * 4);
        acc.x = fmaf(a, w.x, acc.x); acc.y = fmaf(a, w.y, acc.y);
        acc.z = fmaf(a, w.z, acc.z); acc.w = fmaf(a, w.w, acc.w);
    }
#pragma unroll
    for (int off = 16; off; off >>= 1) {
        acc.x += __shfl_xor_sync(0xffffffffu, acc.x, off);
        acc.y += __shfl_xor_sync(0xffffffffu, acc.y, off);
        acc.z += __shfl_xor_sync(0xffffffffu, acc.z, off);
        acc.w += __shfl_xor_sync(0xffffffffu, acc.w, off);
    }
    if (lane == 0) {
        out[row*4+0] = acc.x + b3[0] + prop[row*4+0];
        out[row*4+1] = acc.y + b3[1] + prop[row*4+1];
        out[row*4+2] = acc.z + b3[2] + prop[row*4+2];
        out[row*4+3] = acc.w + b3[3] + prop[row*4+3];
    }
}

// ---------------- top-20 per batch (block per batch) -------------------------
__global__ void topk_kernel(const float* __restrict__ scores, float* __restrict__ scratch,
                            int* __restrict__ topIdx, float* __restrict__ topSc)
{
    int b = blockIdx.x, tid = threadIdx.x;
    const float* s = scores + b * SEQ;
    float* t = scratch + b * SEQ;
    for (int i = tid; i < SEQ; i += blockDim.x) t[i] = s[i];
    __syncthreads();
    __shared__ float rv[1024];
    __shared__ int   ri[1024];
    for (int it = 0; it < NTOP; it++) {
        float bv = -INFINITY; int bi = 0x7fffffff;
        for (int i = tid; i < SEQ; i += blockDim.x) {
            float v = t[i];
            if (v > bv) { bv = v; bi = i; }
        }
        rv[tid] = bv; ri[tid] = bi;
        __syncthreads();
        for (int off = 512; off > 0; off >>= 1) {
            if (tid < off) {
                float ov = rv[tid + off]; int oi = ri[tid + off];
                if (ov > rv[tid] || (ov == rv[tid] && oi < ri[tid])) { rv[tid] = ov; ri[tid] = oi; }
            }
            __syncthreads();
        }
        if (tid == 0) {
            topIdx[b * NTOP + it] = ri[0];
            topSc[b * NTOP + it]  = rv[0];
            t[ri[0]] = -INFINITY;
        }
        __syncthreads();
    }
}

// ---------------- final: gather + sigmoid + boxes + NMS ----------------------
__global__ void final_kernel(const float* __restrict__ logits, const float* __restrict__ coords,
                             const int* __restrict__ topIdx, const float* __restrict__ topSc,
                             const float* __restrict__ WH, float* __restrict__ out)
{
    int b = blockIdx.x, tid = threadIdx.x;
    __shared__ int   idxs[NTOP];
    __shared__ float refp[NTOP][4];
    __shared__ float boxes[NTOP][4];
    if (tid < NTOP) idxs[tid] = topIdx[b * NTOP + tid];
    __syncthreads();

    for (int o = tid; o < NTOP * NC; o += blockDim.x) {
        int k = o / NC, c = o % NC;
        size_t row = (size_t)b * SEQ + idxs[k];
        out[OFF_OUT + b * (NTOP * (NC + 4)) + k * (NC + 4) + c] = logits[row * NC + c];
    }
    if (tid < NTOP * 4) {
        int k = tid >> 2, c = tid & 3;
        size_t row = (size_t)b * SEQ + idxs[k];
        float v = coords[row * 4 + c];
        out[OFF_OUT + b * (NTOP * (NC + 4)) + k * (NC + 4) + NC + c] = v;
        float r = 1.f / (1.f + expf(-v));
        out[OFF_REF + b * (NTOP * 4) + k * 4 + c] = r;
        refp[k][c] = r;
    }
    if (tid < NTOP) out[OFF_SC + b * NTOP + tid] = topSc[b * NTOP + tid];
    __syncthreads();
    if (tid < NTOP) {
        float cx = refp[tid][0], cy = refp[tid][1], w = refp[tid][2], h = refp[tid][3];
        boxes[tid][0] = truncf((cx - 0.5f * w) * WH[b * 4 + 0]);
        boxes[tid][1] = truncf((cy - 0.5f * h) * WH[b * 4 + 1]);
        boxes[tid][2] = truncf((cx + 0.5f * w) * WH[b * 4 + 2]);
        boxes[tid][3] = truncf((cy + 0.5f * h) * WH[b * 4 + 3]);
    }
    __syncthreads();
    if (tid == 0) {
        bool supp[NTOP];
        float area[NTOP];
        for (int k = 0; k < NTOP; k++) {
            supp[k] = false;
            area[k] = (boxes[k][2] - boxes[k][0]) * (boxes[k][3] - boxes[k][1]);
        }
        for (int i = 0; i < NTOP; i++) {
            if (supp[i]) continue;
            for (int j = i + 1; j < NTOP; j++) {
                float xx1 = fmaxf(boxes[i][0], boxes[j][0]);
                float yy1 = fmaxf(boxes[i][1], boxes[j][1]);
                float xx2 = fminf(boxes[i][2], boxes[j][2]);
                float yy2 = fminf(boxes[i][3], boxes[j][3]);
                float inter = fmaxf(xx2 - xx1, 0.f) * fmaxf(yy2 - yy1, 0.f);
                float iou = inter / (area[i] + area[j] - inter);
                if (iou > 0.5f) supp[j] = true;
            }
        }
        for (int k = 0; k < NTOP; k++)
            out[OFF_KEEP + b * NTOP + k] = supp[k] ? 0.f : 1.f;
    }
}

// ---------------- launch -----------------------------------------------------
extern "C" void kernel_launch(void* const* d_in, const int* in_sizes, int n_in,
                              void* d_out, int out_size)
{
    const float* memory        = (const float*)d_in[0];
    const unsigned char* mask  = (const unsigned char*)d_in[1];
    const float* WH            = (const float*)d_in[2];
    const float* W_enc         = (const float*)d_in[3];
    const float* b_enc         = (const float*)d_in[4];
    const float* ln_g          = (const float*)d_in[5];
    const float* ln_b          = (const float*)d_in[6];
    const float* W_cls         = (const float*)d_in[7];
    const float* b_cls         = (const float*)d_in[8];
    const float* W1            = (const float*)d_in[9];
    const float* b1            = (const float*)d_in[10];
    const float* W2            = (const float*)d_in[11];
    const float* b2            = (const float*)d_in[12];
    const float* W3            = (const float*)d_in[13];
    const float* b3            = (const float*)d_in[14];
    float* out = (float*)d_out;

    float *p_tmp, *p_outmem, *p_h1, *p_logits, *p_scores, *p_scratch, *p_prop, *p_coords, *p_topsc;
    unsigned char* p_rowinv; int* p_topidx;
    cudaGetSymbolAddress((void**)&p_tmp,     g_tmp);
    cudaGetSymbolAddress((void**)&p_outmem,  g_outmem);
    cudaGetSymbolAddress((void**)&p_h1,      g_h1);
    cudaGetSymbolAddress((void**)&p_logits,  g_logits);
    cudaGetSymbolAddress((void**)&p_scores,  g_scores);
    cudaGetSymbolAddress((void**)&p_scratch, g_scratch);
    cudaGetSymbolAddress((void**)&p_prop,    g_prop);
    cudaGetSymbolAddress((void**)&p_coords,  g_coords);
    cudaGetSymbolAddress((void**)&p_rowinv,  g_rowinv);
    cudaGetSymbolAddress((void**)&p_topidx,  g_topidx);
    cudaGetSymbolAddress((void**)&p_topsc,   g_topsc);

    props_kernel<<<(MROWS + 255) / 256, 256>>>(mask, p_rowinv, p_prop);

    dim3 gFull((MROWS + 127) / 128, 4);
    dim3 gCls((MROWS + 127) / 128, 2);
    // tmp = mem_masked @ W_enc + b_enc
    sgemm_kernel<<<gFull, 256>>>(memory, W_enc, b_enc, p_tmp, MROWS, CH, 0, p_rowinv);
    // out_mem = LN(tmp)*g + b
    ln_kernel<<<MROWS / 8, 256>>>(p_tmp, ln_g, ln_b, p_outmem);
    // h1 = relu(out_mem @ W1 + b1)
    sgemm_kernel<<<gFull, 256>>>(p_outmem, W1, b1, p_h1, MROWS, CH, 1, nullptr);
    // h2 = relu(h1 @ W2 + b2)  (reuse tmp)
    sgemm_kernel<<<gFull, 256>>>(p_h1, W2, b2, p_tmp, MROWS, CH, 1, nullptr);
    // logits = out_mem @ W_cls + b_cls
    sgemm_kernel<<<gCls, 256>>>(p_outmem, W_cls, b_cls, p_logits, MROWS, NC, 0, nullptr);
    // scores = rowmax(logits)
    rowmax_kernel<<<SEQ, 256>>>(p_logits, p_scores);
    // coords = h2 @ W3 + b3 + prop
    coords_kernel<<<SEQ, 256>>>(p_tmp, W3, b3, p_prop, p_coords);
    // top-20 per batch
    topk_kernel<<<BSZ, 1024>>>(p_scores, p_scratch, p_topidx, p_topsc);
    // gather + sigmoid + NMS + writes
    final_kernel<<<BSZ, 128>>>(p_logits, p_coords, p_topidx, p_topsc, WH, out);

    (void)in_sizes; (void)n_in; (void)out_size;
}

// round 8
// speedup vs baseline: 1.5805x; 1.1608x over previous
#include <cuda_runtime.h>
#include <math.h>
#include <stdint.h>

#define BSZ   8
#define SEQ   19947
#define MROWS 159576          // BSZ*SEQ
#define CH    256
#define NC    91
#define NTOP  20

// output layout (float32, concatenated flattened tuple)
#define OFF_OUT  0            // (8,20,95)
#define OFF_REF  15200        // (8,20,4)
#define OFF_KEEP 15840        // (8,20)
#define OFF_SC   16000        // (8,20)

// ---------------- scratch (device globals: allocation-free) ----------------
__device__ float g_tmp[MROWS * CH];      // G1 out (pre-LN), later h2
__device__ float g_outmem[MROWS * CH];
__device__ float g_h1[MROWS * CH];
__device__ float g_logits[MROWS * NC];
__device__ float g_scores[MROWS];
__device__ float g_scratch[MROWS];
__device__ float g_prop[MROWS * 4];
__device__ float g_coords[MROWS * 4];
__device__ unsigned char g_rowinv[MROWS];
__device__ int   g_topidx[BSZ * NTOP];
__device__ float g_topsc[BSZ * NTOP];

// ---------------- packed f32x2 helpers (Blackwell FFMA2) -------------------
__device__ __forceinline__ unsigned long long ffma2(unsigned long long a,
                                                    unsigned long long b,
                                                    unsigned long long c)
{
    unsigned long long d;
    asm("fma.rn.f32x2 %0, %1, %2, %3;" : "=l"(d) : "l"(a), "l"(b), "l"(c));
    return d;
}
__device__ __forceinline__ unsigned long long bcast2(float x)
{
    unsigned long long d;
    unsigned int xi = __float_as_uint(x);
    asm("mov.b64 %0, {%1, %1};" : "=l"(d) : "r"(xi));
    return d;
}

// ---------------- kernel 0: proposal logits + row invalid flags ------------
__global__ void props_kernel(const unsigned char* __restrict__ mask,
                             unsigned char* __restrict__ rowInv,
                             float* __restrict__ prop)
{
    int row = blockIdx.x * blockDim.x + threadIdx.x;
    if (row >= MROWS) return;
    int s = row % SEQ;
    int Hh, Ww, lvl, t;
    if (s < 15000)      { lvl = 0; Hh = 100; Ww = 150; t = s; }
    else if (s < 18750) { lvl = 1; Hh = 50;  Ww = 75;  t = s - 15000; }
    else if (s < 19700) { lvl = 2; Hh = 25;  Ww = 38;  t = s - 18750; }
    else                { lvl = 3; Hh = 13;  Ww = 19;  t = s - 19700; }
    int y = t / Ww, x = t % Ww;
    float cx = ((float)x + 0.5f) / (float)Ww;
    float cy = ((float)y + 0.5f) / (float)Hh;
    float wh = 0.05f * (float)(1 << lvl);
    bool valid = (cx > 0.01f) && (cx < 0.99f) &&
                 (cy > 0.01f) && (cy < 0.99f) &&
                 (wh > 0.01f) && (wh < 0.99f);
    bool inv = (mask[row] != 0) || !valid;
    rowInv[row] = inv ? 1 : 0;
    if (inv) {
        prop[row*4+0] = INFINITY; prop[row*4+1] = INFINITY;
        prop[row*4+2] = INFINITY; prop[row*4+3] = INFINITY;
    } else {
        float lw = logf(wh / (1.f - wh));
        prop[row*4+0] = logf(cx / (1.f - cx));
        prop[row*4+1] = logf(cy / (1.f - cy));
        prop[row*4+2] = lw;
        prop[row*4+3] = lw;
    }
}

// ---------------- SGEMM: C = act(A[M,256] @ B[256,N] + bias) ---------------
__device__ __forceinline__ float4 loadA4(const float* __restrict__ A, int gr, int kOff,
                                         int M, const unsigned char* __restrict__ rowInv)
{
    if (gr < M && (rowInv == nullptr || rowInv[gr] == 0))
        return *reinterpret_cast<const float4*>(A + (size_t)gr * CH + kOff);
    return make_float4(0.f, 0.f, 0.f, 0.f);
}
__device__ __forceinline__ float4 loadB4(const float* __restrict__ Bm, int k, int gc, int N)
{
    if ((N & 3) == 0)  // N=256 path: always in-bounds & 16B aligned
        return *reinterpret_cast<const float4*>(Bm + (size_t)k * N + gc);
    float4 v;
    v.x = (gc + 0 < N) ? Bm[(size_t)k * N + gc + 0] : 0.f;
    v.y = (gc + 1 < N) ? Bm[(size_t)k * N + gc + 1] : 0.f;
    v.z = (gc + 2 < N) ? Bm[(size_t)k * N + gc + 2] : 0.f;
    v.w = (gc + 3 < N) ? Bm[(size_t)k * N + gc + 3] : 0.f;
    return v;
}

__global__ void __launch_bounds__(256)
sgemm_kernel(const float* __restrict__ A, const float* __restrict__ Bm,
             const float* __restrict__ bias, float* __restrict__ C,
             int M, int N, int act, const unsigned char* __restrict__ rowInv)
{
    __shared__ float As[2][16][128 + 4];
    __shared__ float Bs[2][16][64];

    const int tid = threadIdx.x;
    const int rowBase = blockIdx.x * 128;
    const int colBase = blockIdx.y * 64;

    const int warp = tid >> 5, lane = tid & 31;
    const int tRow = (warp & 3) * 32 + (lane & 3) * 8;   // 8 rows (4 packed pairs)
    const int tCol = (warp >> 2) * 32 + (lane >> 2) * 4; // 4 cols

    const int aRow0 = tid >> 2,          aK0 = (tid & 3) << 2;
    const int aRow1 = (tid + 256) >> 2,  aK1 = (tid & 3) << 2; // (tid+256)&3 == tid&3
    const int bK = tid >> 4, bN = (tid & 15) << 2;

    // packed accumulators: acc2[r2][c] holds rows (tRow+2*r2, tRow+2*r2+1), col tCol+c
    unsigned long long acc2[4][4];
#pragma unroll
    for (int r = 0; r < 4; r++)
#pragma unroll
        for (int c = 0; c < 4; c++) acc2[r][c] = 0ull;

    float4 a0r = loadA4(A, rowBase + aRow0, aK0, M, rowInv);
    float4 a1r = loadA4(A, rowBase + aRow1, aK1, M, rowInv);
    float4 b0r = loadB4(Bm, bK, colBase + bN, N);
    As[0][aK0+0][aRow0] = a0r.x; As[0][aK0+1][aRow0] = a0r.y;
    As[0][aK0+2][aRow0] = a0r.z; As[0][aK0+3][aRow0] = a0r.w;
    As[0][aK1+0][aRow1] = a1r.x; As[0][aK1+1][aRow1] = a1r.y;
    As[0][aK1+2][aRow1] = a1r.z; As[0][aK1+3][aRow1] = a1r.w;
    *reinterpret_cast<float4*>(&Bs[0][bK][bN]) = b0r;
    __syncthreads();

#pragma unroll 1
    for (int kb = 0; kb < 16; kb++) {
        const int cur = kb & 1;
        if (kb < 15) {
            a0r = loadA4(A, rowBase + aRow0, (kb + 1) * 16 + aK0, M, rowInv);
            a1r = loadA4(A, rowBase + aRow1, (kb + 1) * 16 + aK1, M, rowInv);
            b0r = loadB4(Bm, (kb + 1) * 16 + bK, colBase + bN, N);
        }
#pragma unroll
        for (int kk = 0; kk < 16; kk++) {
            // A fragment: 8 rows = 4 packed f32x2 pairs (adjacent rows adjacent in As)
            ulonglong2 a01 = *reinterpret_cast<const ulonglong2*>(&As[cur][kk][tRow]);
            ulonglong2 a23 = *reinterpret_cast<const ulonglong2*>(&As[cur][kk][tRow + 4]);
            float4 b  = *reinterpret_cast<const float4*>(&Bs[cur][kk][tCol]);
            unsigned long long av[4] = {a01.x, a01.y, a23.x, a23.y};
            unsigned long long bv[4] = {bcast2(b.x), bcast2(b.y), bcast2(b.z), bcast2(b.w)};
#pragma unroll
            for (int r = 0; r < 4; r++)
#pragma unroll
                for (int c = 0; c < 4; c++)
                    acc2[r][c] = ffma2(av[r], bv[c], acc2[r][c]);
        }
        if (kb < 15) {
            const int nxt = 1 - cur;
            As[nxt][aK0+0][aRow0] = a0r.x; As[nxt][aK0+1][aRow0] = a0r.y;
            As[nxt][aK0+2][aRow0] = a0r.z; As[nxt][aK0+3][aRow0] = a0r.w;
            As[nxt][aK1+0][aRow1] = a1r.x; As[nxt][aK1+1][aRow1] = a1r.y;
            As[nxt][aK1+2][aRow1] = a1r.z; As[nxt][aK1+3][aRow1] = a1r.w;
            *reinterpret_cast<float4*>(&Bs[nxt][bK][bN]) = b0r;
            __syncthreads();
        }
    }

#pragma unroll
    for (int r2 = 0; r2 < 4; r2++) {
#pragma unroll
        for (int half = 0; half < 2; half++) {
            int gr = rowBase + tRow + 2 * r2 + half;
            if (gr >= M) continue;
#pragma unroll
            for (int c = 0; c < 4; c++) {
                int gc = colBase + tCol + c;
                if (gc >= N) continue;
                float2 pair = *reinterpret_cast<const float2*>(&acc2[r2][c]);
                float v = (half == 0 ? pair.x : pair.y) + bias[gc];
                if (act) v = fmaxf(v, 0.f);
                C[(size_t)gr * N + gc] = v;
            }
        }
    }
}

// ---------------- LayerNorm (warp per row) ----------------------------------
__global__ void ln_kernel(const float* __restrict__ X, const float* __restrict__ g,
                          const float* __restrict__ b, float* __restrict__ Y)
{
    int row = (blockIdx.x * blockDim.x + threadIdx.x) >> 5;
    if (row >= MROWS) return;
    int lane = threadIdx.x & 31;
    const float* x = X + (size_t)row * CH + lane * 8;
    float4 v0 = *reinterpret_cast<const float4*>(x);
    float4 v1 = *reinterpret_cast<const float4*>(x + 4);
    float s = v0.x+v0.y+v0.z+v0.w + v1.x+v1.y+v1.z+v1.w;
#pragma unroll
    for (int off = 16; off; off >>= 1) s += __shfl_xor_sync(0xffffffffu, s, off);
    float mean = s * (1.f / 256.f);
    float d0 = v0.x-mean, d1 = v0.y-mean, d2 = v0.z-mean, d3 = v0.w-mean;
    float d4 = v1.x-mean, d5 = v1.y-mean, d6 = v1.z-mean, d7 = v1.w-mean;
    float q = d0*d0+d1*d1+d2*d2+d3*d3+d4*d4+d5*d5+d6*d6+d7*d7;
#pragma unroll
    for (int off = 16; off; off >>= 1) q += __shfl_xor_sync(0xffffffffu, q, off);
    float var = q * (1.f / 256.f);
    float inv = 1.f / sqrtf(var + 1e-5f);
    float4 gg0 = *reinterpret_cast<const float4*>(g + lane * 8);
    float4 gg1 = *reinterpret_cast<const float4*>(g + lane * 8 + 4);
    float4 bb0 = *reinterpret_cast<const float4*>(b + lane * 8);
    float4 bb1 = *reinterpret_cast<const float4*>(b + lane * 8 + 4);
    float4 o0, o1;
    o0.x = d0*inv*gg0.x + bb0.x; o0.y = d1*inv*gg0.y + bb0.y;
    o0.z = d2*inv*gg0.z + bb0.z; o0.w = d3*inv*gg0.w + bb0.w;
    o1.x = d4*inv*gg1.x + bb1.x; o1.y = d5*inv*gg1.y + bb1.y;
    o1.z = d6*inv*gg1.z + bb1.z; o1.w = d7*inv*gg1.w + bb1.w;
    float* y = Y + (size_t)row * CH + lane * 8;
    *reinterpret_cast<float4*>(y) = o0;
    *reinterpret_cast<float4*>(y + 4) = o1;
}

// ---------------- row-max of logits (warp per row) --------------------------
__global__ void rowmax_kernel(const float* __restrict__ logits, float* __restrict__ scores)
{
    int row = (blockIdx.x * blockDim.x + threadIdx.x) >> 5;
    if (row >= MROWS) return;
    int lane = threadIdx.x & 31;
    float m = -INFINITY;
    for (int c = lane; c < NC; c += 32) m = fmaxf(m, logits[(size_t)row * NC + c]);
#pragma unroll
    for (int off = 16; off; off >>= 1) m = fmaxf(m, __shfl_xor_sync(0xffffffffu, m, off));
    if (lane == 0) scores[row] = m;
}

// ---------------- coords = h2 @ W3 + b3 + prop (warp per row) ---------------
__global__ void coords_kernel(const float* __restrict__ H2, const float* __restrict__ W3,
                              const float* __restrict__ b3, const float* __restrict__ prop,
                              float* __restrict__ out)
{
    int row = (blockIdx.x * blockDim.x + threadIdx.x) >> 5;
    if (row >= MROWS) return;
    int lane = threadIdx.x & 31;
    const float* h = H2 + (size_t)row * CH;
    float4 acc = make_float4(0.f, 0.f, 0.f, 0.f);
    for (int k = lane; k < CH; k += 32) {
        float a = h[k];
        float4 w = *reinterpret_cast<const float4*>(W3 + k * 4);
        acc.x = fmaf(a, w.x, acc.x); acc.y = fmaf(a, w.y, acc.y);
        acc.z = fmaf(a, w.z, acc.z); acc.w = fmaf(a, w.w, acc.w);
    }
#pragma unroll
    for (int off = 16; off; off >>= 1) {
        acc.x += __shfl_xor_sync(0xffffffffu, acc.x, off);
        acc.y += __shfl_xor_sync(0xffffffffu, acc.y, off);
        acc.z += __shfl_xor_sync(0xffffffffu, acc.z, off);
        acc.w += __shfl_xor_sync(0xffffffffu, acc.w, off);
    }
    if (lane == 0) {
        out[row*4+0] = acc.x + b3[0] + prop[row*4+0];
        out[row*4+1] = acc.y + b3[1] + prop[row*4+1];
        out[row*4+2] = acc.z + b3[2] + prop[row*4+2];
        out[row*4+3] = acc.w + b3[3] + prop[row*4+3];
    }
}

// ---------------- top-20 per batch (block per batch) -------------------------
__global__ void topk_kernel(const float* __restrict__ scores, float* __restrict__ scratch,
                            int* __restrict__ topIdx, float* __restrict__ topSc)
{
    int b = blockIdx.x, tid = threadIdx.x;
    const float* s = scores + b * SEQ;
    float* t = scratch + b * SEQ;
    for (int i = tid; i < SEQ; i += blockDim.x) t[i] = s[i];
    __syncthreads();
    __shared__ float rv[1024];
    __shared__ int   ri[1024];
    for (int it = 0; it < NTOP; it++) {
        float bv = -INFINITY; int bi = 0x7fffffff;
        for (int i = tid; i < SEQ; i += blockDim.x) {
            float v = t[i];
            if (v > bv) { bv = v; bi = i; }
        }
        rv[tid] = bv; ri[tid] = bi;
        __syncthreads();
        for (int off = 512; off > 0; off >>= 1) {
            if (tid < off) {
                float ov = rv[tid + off]; int oi = ri[tid + off];
                if (ov > rv[tid] || (ov == rv[tid] && oi < ri[tid])) { rv[tid] = ov; ri[tid] = oi; }
            }
            __syncthreads();
        }
        if (tid == 0) {
            topIdx[b * NTOP + it] = ri[0];
            topSc[b * NTOP + it]  = rv[0];
            t[ri[0]] = -INFINITY;
        }
        __syncthreads();
    }
}

// ---------------- final: gather + sigmoid + boxes + NMS ----------------------
__global__ void final_kernel(const float* __restrict__ logits, const float* __restrict__ coords,
                             const int* __restrict__ topIdx, const float* __restrict__ topSc,
                             const float* __restrict__ WH, float* __restrict__ out)
{
    int b = blockIdx.x, tid = threadIdx.x;
    __shared__ int   idxs[NTOP];
    __shared__ float refp[NTOP][4];
    __shared__ float boxes[NTOP][4];
    if (tid < NTOP) idxs[tid] = topIdx[b * NTOP + tid];
    __syncthreads();

    for (int o = tid; o < NTOP * NC; o += blockDim.x) {
        int k = o / NC, c = o % NC;
        size_t row = (size_t)b * SEQ + idxs[k];
        out[OFF_OUT + b * (NTOP * (NC + 4)) + k * (NC + 4) + c] = logits[row * NC + c];
    }
    if (tid < NTOP * 4) {
        int k = tid >> 2, c = tid & 3;
        size_t row = (size_t)b * SEQ + idxs[k];
        float v = coords[row * 4 + c];
        out[OFF_OUT + b * (NTOP * (NC + 4)) + k * (NC + 4) + NC + c] = v;
        float r = 1.f / (1.f + expf(-v));
        out[OFF_REF + b * (NTOP * 4) + k * 4 + c] = r;
        refp[k][c] = r;
    }
    if (tid < NTOP) out[OFF_SC + b * NTOP + tid] = topSc[b * NTOP + tid];
    __syncthreads();
    if (tid < NTOP) {
        float cx = refp[tid][0], cy = refp[tid][1], w = refp[tid][2], h = refp[tid][3];
        boxes[tid][0] = truncf((cx - 0.5f * w) * WH[b * 4 + 0]);
        boxes[tid][1] = truncf((cy - 0.5f * h) * WH[b * 4 + 1]);
        boxes[tid][2] = truncf((cx + 0.5f * w) * WH[b * 4 + 2]);
        boxes[tid][3] = truncf((cy + 0.5f * h) * WH[b * 4 + 3]);
    }
    __syncthreads();
    if (tid == 0) {
        bool supp[NTOP];
        float area[NTOP];
        for (int k = 0; k < NTOP; k++) {
            supp[k] = false;
            area[k] = (boxes[k][2] - boxes[k][0]) * (boxes[k][3] - boxes[k][1]);
        }
        for (int i = 0; i < NTOP; i++) {
            if (supp[i]) continue;
            for (int j = i + 1; j < NTOP; j++) {
                float xx1 = fmaxf(boxes[i][0], boxes[j][0]);
                float yy1 = fmaxf(boxes[i][1], boxes[j][1]);
                float xx2 = fminf(boxes[i][2], boxes[j][2]);
                float yy2 = fminf(boxes[i][3], boxes[j][3]);
                float inter = fmaxf(xx2 - xx1, 0.f) * fmaxf(yy2 - yy1, 0.f);
                float iou = inter / (area[i] + area[j] - inter);
                if (iou > 0.5f) supp[j] = true;
            }
        }
        for (int k = 0; k < NTOP; k++)
            out[OFF_KEEP + b * NTOP + k] = supp[k] ? 0.f : 1.f;
    }
}

// ---------------- launch -----------------------------------------------------
extern "C" void kernel_launch(void* const* d_in, const int* in_sizes, int n_in,
                              void* d_out, int out_size)
{
    const float* memory        = (const float*)d_in[0];
    const unsigned char* mask  = (const unsigned char*)d_in[1];
    const float* WH            = (const float*)d_in[2];
    const float* W_enc         = (const float*)d_in[3];
    const float* b_enc         = (const float*)d_in[4];
    const float* ln_g          = (const float*)d_in[5];
    const float* ln_b          = (const float*)d_in[6];
    const float* W_cls         = (const float*)d_in[7];
    const float* b_cls         = (const float*)d_in[8];
    const float* W1            = (const float*)d_in[9];
    const float* b1            = (const float*)d_in[10];
    const float* W2            = (const float*)d_in[11];
    const float* b2            = (const float*)d_in[12];
    const float* W3            = (const float*)d_in[13];
    const float* b3            = (const float*)d_in[14];
    float* out = (float*)d_out;

    float *p_tmp, *p_outmem, *p_h1, *p_logits, *p_scores, *p_scratch, *p_prop, *p_coords, *p_topsc;
    unsigned char* p_rowinv; int* p_topidx;
    cudaGetSymbolAddress((void**)&p_tmp,     g_tmp);
    cudaGetSymbolAddress((void**)&p_outmem,  g_outmem);
    cudaGetSymbolAddress((void**)&p_h1,      g_h1);
    cudaGetSymbolAddress((void**)&p_logits,  g_logits);
    cudaGetSymbolAddress((void**)&p_scores,  g_scores);
    cudaGetSymbolAddress((void**)&p_scratch, g_scratch);
    cudaGetSymbolAddress((void**)&p_prop,    g_prop);
    cudaGetSymbolAddress((void**)&p_coords,  g_coords);
    cudaGetSymbolAddress((void**)&p_rowinv,  g_rowinv);
    cudaGetSymbolAddress((void**)&p_topidx,  g_topidx);
    cudaGetSymbolAddress((void**)&p_topsc,   g_topsc);

    props_kernel<<<(MROWS + 255) / 256, 256>>>(mask, p_rowinv, p_prop);

    dim3 gFull((MROWS + 127) / 128, 4);
    dim3 gCls((MROWS + 127) / 128, 2);
    // tmp = mem_masked @ W_enc + b_enc
    sgemm_kernel<<<gFull, 256>>>(memory, W_enc, b_enc, p_tmp, MROWS, CH, 0, p_rowinv);
    // out_mem = LN(tmp)*g + b
    ln_kernel<<<MROWS / 8, 256>>>(p_tmp, ln_g, ln_b, p_outmem);
    // h1 = relu(out_mem @ W1 + b1)
    sgemm_kernel<<<gFull, 256>>>(p_outmem, W1, b1, p_h1, MROWS, CH, 1, nullptr);
    // h2 = relu(h1 @ W2 + b2)  (reuse tmp)
    sgemm_kernel<<<gFull, 256>>>(p_h1, W2, b2, p_tmp, MROWS, CH, 1, nullptr);
    // logits = out_mem @ W_cls + b_cls
    sgemm_kernel<<<gCls, 256>>>(p_outmem, W_cls, b_cls, p_logits, MROWS, NC, 0, nullptr);
    // scores = rowmax(logits)
    rowmax_kernel<<<SEQ, 256>>>(p_logits, p_scores);
    // coords = h2 @ W3 + b3 + prop
    coords_kernel<<<SEQ, 256>>>(p_tmp, W3, b3, p_prop, p_coords);
    // top-20 per batch
    topk_kernel<<<BSZ, 1024>>>(p_scores, p_scratch, p_topidx, p_topsc);
    // gather + sigmoid + NMS + writes
    final_kernel<<<BSZ, 128>>>(p_logits, p_coords, p_topidx, p_topsc, WH, out);

    (void)in_sizes; (void)n_in; (void)out_size;
}

// round 9
// speedup vs baseline: 1.6847x; 1.0659x over previous
#include <cuda_runtime.h>
#include <math.h>
#include <stdint.h>
#include <string.h>

#define BSZ   8
#define SEQ   19947
#define MROWS 159576          // BSZ*SEQ
#define CH    256
#define NC    91
#define NTOP  20

// output layout (float32, concatenated flattened tuple)
#define OFF_OUT  0            // (8,20,95)
#define OFF_REF  15200        // (8,20,4)
#define OFF_KEEP 15840        // (8,20)
#define OFF_SC   16000        // (8,20)

// ---------------- scratch (device globals: allocation-free) ----------------
__device__ float g_tmp[MROWS * CH];      // G1 out (pre-LN), later h2
__device__ float g_outmem[MROWS * CH];
__device__ float g_h1[MROWS * CH];
__device__ float g_logits[MROWS * NC];
__device__ float g_scores[MROWS];
__device__ float g_scratch[MROWS];
__device__ float g_prop[MROWS * 4];
__device__ float g_coords[MROWS * 4];
__device__ unsigned char g_rowinv[MROWS];
__device__ int   g_topidx[BSZ * NTOP];
__device__ float g_topsc[BSZ * NTOP];

// ---------------- packed f32x2 helpers (Blackwell FFMA2) -------------------
__device__ __forceinline__ unsigned long long ffma2(unsigned long long a,
                                                    unsigned long long b,
                                                    unsigned long long c)
{
    unsigned long long d;
    asm("fma.rn.f32x2 %0, %1, %2, %3;" : "=l"(d) : "l"(a), "l"(b), "l"(c));
    return d;
}
__device__ __forceinline__ unsigned long long bcast2(float x)
{
    unsigned long long d;
    unsigned int xi = __float_as_uint(x);
    asm("mov.b64 %0, {%1, %1};" : "=l"(d) : "r"(xi));
    return d;
}
__device__ __forceinline__ float pickhalf(unsigned long long v, int half)
{
    float2 p;
    memcpy(&p, &v, 8);
    return half ? p.y : p.x;
}

// ---------------- kernel 0: proposal logits + row invalid flags ------------
__global__ void props_kernel(const unsigned char* __restrict__ mask,
                             unsigned char* __restrict__ rowInv,
                             float* __restrict__ prop)
{
    int row = blockIdx.x * blockDim.x + threadIdx.x;
    if (row >= MROWS) return;
    int s = row % SEQ;
    int Hh, Ww, lvl, t;
    if (s < 15000)      { lvl = 0; Hh = 100; Ww = 150; t = s; }
    else if (s < 18750) { lvl = 1; Hh = 50;  Ww = 75;  t = s - 15000; }
    else if (s < 19700) { lvl = 2; Hh = 25;  Ww = 38;  t = s - 18750; }
    else                { lvl = 3; Hh = 13;  Ww = 19;  t = s - 19700; }
    int y = t / Ww, x = t % Ww;
    float cx = ((float)x + 0.5f) / (float)Ww;
    float cy = ((float)y + 0.5f) / (float)Hh;
    float wh = 0.05f * (float)(1 << lvl);
    bool valid = (cx > 0.01f) && (cx < 0.99f) &&
                 (cy > 0.01f) && (cy < 0.99f) &&
                 (wh > 0.01f) && (wh < 0.99f);
    bool inv = (mask[row] != 0) || !valid;
    rowInv[row] = inv ? 1 : 0;
    if (inv) {
        prop[row*4+0] = INFINITY; prop[row*4+1] = INFINITY;
        prop[row*4+2] = INFINITY; prop[row*4+3] = INFINITY;
    } else {
        float lw = logf(wh / (1.f - wh));
        prop[row*4+0] = logf(cx / (1.f - cx));
        prop[row*4+1] = logf(cy / (1.f - cy));
        prop[row*4+2] = lw;
        prop[row*4+3] = lw;
    }
}

// ---------------- SGEMM: C = act(A[M,256] @ B[256,N] + bias) ---------------
// 128x128 block tile, 256 threads, 8x8 microtile, packed f32x2 accumulators.
__device__ __forceinline__ float4 loadA4(const float* __restrict__ A, int gr, int kOff,
                                         int M, const unsigned char* __restrict__ rowInv)
{
    if (gr < M && (rowInv == nullptr || rowInv[gr] == 0))
        return *reinterpret_cast<const float4*>(A + (size_t)gr * CH + kOff);
    return make_float4(0.f, 0.f, 0.f, 0.f);
}
__device__ __forceinline__ float4 loadB4(const float* __restrict__ Bm, int k, int gc, int N)
{
    if ((N & 3) == 0 && gc + 3 < N)
        return *reinterpret_cast<const float4*>(Bm + (size_t)k * N + gc);
    float4 v;
    v.x = (gc + 0 < N) ? Bm[(size_t)k * N + gc + 0] : 0.f;
    v.y = (gc + 1 < N) ? Bm[(size_t)k * N + gc + 1] : 0.f;
    v.z = (gc + 2 < N) ? Bm[(size_t)k * N + gc + 2] : 0.f;
    v.w = (gc + 3 < N) ? Bm[(size_t)k * N + gc + 3] : 0.f;
    return v;
}

__global__ void __launch_bounds__(256, 2)
sgemm2_kernel(const float* __restrict__ A, const float* __restrict__ Bm,
              const float* __restrict__ bias, float* __restrict__ C,
              int M, int N, int act, const unsigned char* __restrict__ rowInv,
              float* __restrict__ scores)
{
    __shared__ float As[2][16][128 + 4];
    __shared__ float Bs[2][16][128 + 4];

    const int tid = threadIdx.x;
    const int rowBase = blockIdx.x * 128;
    const int colBase = blockIdx.y * 128;

    const int warp = tid >> 5, lane = tid & 31;
    const int tRow = (warp & 3) * 32 + (lane & 3) * 8;   // 8 rows (4 packed pairs)
    const int tCol = (warp >> 2) * 64 + (lane >> 2) * 8; // 8 cols

    // A loaders: 128 rows x 16 k = 512 float4, 2 per thread
    const int aRow0 = tid >> 2, aK = (tid & 3) << 2, aRow1 = aRow0 + 64;
    // B loaders: 16 k x 128 cols = 512 float4, 2 per thread
    const int bK0 = tid >> 5, bN = (tid & 31) << 2, bK1 = bK0 + 8;

    unsigned long long acc2[4][8];
#pragma unroll
    for (int r = 0; r < 4; r++)
#pragma unroll
        for (int c = 0; c < 8; c++) acc2[r][c] = 0ull;

    float4 a0r = loadA4(A, rowBase + aRow0, aK, M, rowInv);
    float4 a1r = loadA4(A, rowBase + aRow1, aK, M, rowInv);
    float4 b0r = loadB4(Bm, bK0, colBase + bN, N);
    float4 b1r = loadB4(Bm, bK1, colBase + bN, N);
    As[0][aK+0][aRow0] = a0r.x; As[0][aK+1][aRow0] = a0r.y;
    As[0][aK+2][aRow0] = a0r.z; As[0][aK+3][aRow0] = a0r.w;
    As[0][aK+0][aRow1] = a1r.x; As[0][aK+1][aRow1] = a1r.y;
    As[0][aK+2][aRow1] = a1r.z; As[0][aK+3][aRow1] = a1r.w;
    *reinterpret_cast<float4*>(&Bs[0][bK0][bN]) = b0r;
    *reinterpret_cast<float4*>(&Bs[0][bK1][bN]) = b1r;
    __syncthreads();

#pragma unroll 1
    for (int kb = 0; kb < 16; kb++) {
        const int cur = kb & 1;
        if (kb < 15) {
            a0r = loadA4(A, rowBase + aRow0, (kb + 1) * 16 + aK, M, rowInv);
            a1r = loadA4(A, rowBase + aRow1, (kb + 1) * 16 + aK, M, rowInv);
            b0r = loadB4(Bm, (kb + 1) * 16 + bK0, colBase + bN, N);
            b1r = loadB4(Bm, (kb + 1) * 16 + bK1, colBase + bN, N);
        }
#pragma unroll
        for (int kk = 0; kk < 16; kk++) {
            ulonglong2 a01 = *reinterpret_cast<const ulonglong2*>(&As[cur][kk][tRow]);
            ulonglong2 a23 = *reinterpret_cast<const ulonglong2*>(&As[cur][kk][tRow + 4]);
            float4 b0 = *reinterpret_cast<const float4*>(&Bs[cur][kk][tCol]);
            float4 b1 = *reinterpret_cast<const float4*>(&Bs[cur][kk][tCol + 4]);
            unsigned long long av[4] = {a01.x, a01.y, a23.x, a23.y};
            float bf[8] = {b0.x, b0.y, b0.z, b0.w, b1.x, b1.y, b1.z, b1.w};
#pragma unroll
            for (int c = 0; c < 8; c++) {
                unsigned long long bc = bcast2(bf[c]);
#pragma unroll
                for (int r = 0; r < 4; r++)
                    acc2[r][c] = ffma2(av[r], bc, acc2[r][c]);
            }
        }
        if (kb < 15) {
            const int nxt = 1 - cur;
            As[nxt][aK+0][aRow0] = a0r.x; As[nxt][aK+1][aRow0] = a0r.y;
            As[nxt][aK+2][aRow0] = a0r.z; As[nxt][aK+3][aRow0] = a0r.w;
            As[nxt][aK+0][aRow1] = a1r.x; As[nxt][aK+1][aRow1] = a1r.y;
            As[nxt][aK+2][aRow1] = a1r.z; As[nxt][aK+3][aRow1] = a1r.w;
            *reinterpret_cast<float4*>(&Bs[nxt][bK0][bN]) = b0r;
            *reinterpret_cast<float4*>(&Bs[nxt][bK1][bN]) = b1r;
            __syncthreads();
        }
    }

    // ---- epilogue: bias + optional relu, vectorized when possible ----
    const int gcBase = colBase + tCol;
    if ((N & 3) == 0 && gcBase + 7 < N) {
        float4 bb0 = *reinterpret_cast<const float4*>(&bias[gcBase]);
        float4 bb1 = *reinterpret_cast<const float4*>(&bias[gcBase + 4]);
#pragma unroll
        for (int r2 = 0; r2 < 4; r2++) {
#pragma unroll
            for (int half = 0; half < 2; half++) {
                int gr = rowBase + tRow + 2 * r2 + half;
                if (gr >= M) continue;
                float4 v0, v1;
                v0.x = pickhalf(acc2[r2][0], half) + bb0.x;
                v0.y = pickhalf(acc2[r2][1], half) + bb0.y;
                v0.z = pickhalf(acc2[r2][2], half) + bb0.z;
                v0.w = pickhalf(acc2[r2][3], half) + bb0.w;
                v1.x = pickhalf(acc2[r2][4], half) + bb1.x;
                v1.y = pickhalf(acc2[r2][5], half) + bb1.y;
                v1.z = pickhalf(acc2[r2][6], half) + bb1.z;
                v1.w = pickhalf(acc2[r2][7], half) + bb1.w;
                if (act) {
                    v0.x = fmaxf(v0.x, 0.f); v0.y = fmaxf(v0.y, 0.f);
                    v0.z = fmaxf(v0.z, 0.f); v0.w = fmaxf(v0.w, 0.f);
                    v1.x = fmaxf(v1.x, 0.f); v1.y = fmaxf(v1.y, 0.f);
                    v1.z = fmaxf(v1.z, 0.f); v1.w = fmaxf(v1.w, 0.f);
                }
                *reinterpret_cast<float4*>(&C[(size_t)gr * N + gcBase]) = v0;
                *reinterpret_cast<float4*>(&C[(size_t)gr * N + gcBase + 4]) = v1;
            }
        }
    } else {
#pragma unroll
        for (int r2 = 0; r2 < 4; r2++) {
#pragma unroll
            for (int half = 0; half < 2; half++) {
                int gr = rowBase + tRow + 2 * r2 + half;
                if (gr >= M) continue;
#pragma unroll
                for (int c = 0; c < 8; c++) {
                    int gc = gcBase + c;
                    if (gc >= N) continue;
                    float v = pickhalf(acc2[r2][c], half) + bias[gc];
                    if (act) v = fmaxf(v, 0.f);
                    C[(size_t)gr * N + gc] = v;
                }
            }
        }
    }

    // ---- fused row-max (cls GEMM: whole N fits in one column-block) ----
    if (scores != nullptr) {
        __syncthreads();                       // all warps done reading As
        float* red = &As[0][0][0];             // reuse as [128][16]
        int slot = ((warp >> 2) << 3) | (lane >> 2);
#pragma unroll
        for (int r2 = 0; r2 < 4; r2++) {
#pragma unroll
            for (int half = 0; half < 2; half++) {
                int lr = tRow + 2 * r2 + half;
                float m = -INFINITY;
#pragma unroll
                for (int c = 0; c < 8; c++) {
                    int gc = gcBase + c;
                    if (gc < N)
                        m = fmaxf(m, pickhalf(acc2[r2][c], half) + bias[gc]);
                }
                red[lr * 16 + slot] = m;
            }
        }
        __syncthreads();
        if (tid < 128) {
            int gr = rowBase + tid;
            if (gr < M) {
                float m = -INFINITY;
#pragma unroll
                for (int s = 0; s < 16; s++) m = fmaxf(m, red[tid * 16 + s]);
                scores[gr] = m;
            }
        }
    }
}

// ---------------- LayerNorm (warp per row) ----------------------------------
__global__ void ln_kernel(const float* __restrict__ X, const float* __restrict__ g,
                          const float* __restrict__ b, float* __restrict__ Y)
{
    int row = (blockIdx.x * blockDim.x + threadIdx.x) >> 5;
    if (row >= MROWS) return;
    int lane = threadIdx.x & 31;
    const float* x = X + (size_t)row * CH + lane * 8;
    float4 v0 = *reinterpret_cast<const float4*>(x);
    float4 v1 = *reinterpret_cast<const float4*>(x + 4);
    float s = v0.x+v0.y+v0.z+v0.w + v1.x+v1.y+v1.z+v1.w;
#pragma unroll
    for (int off = 16; off; off >>= 1) s += __shfl_xor_sync(0xffffffffu, s, off);
    float mean = s * (1.f / 256.f);
    float d0 = v0.x-mean, d1 = v0.y-mean, d2 = v0.z-mean, d3 = v0.w-mean;
    float d4 = v1.x-mean, d5 = v1.y-mean, d6 = v1.z-mean, d7 = v1.w-mean;
    float q = d0*d0+d1*d1+d2*d2+d3*d3+d4*d4+d5*d5+d6*d6+d7*d7;
#pragma unroll
    for (int off = 16; off; off >>= 1) q += __shfl_xor_sync(0xffffffffu, q, off);
    float var = q * (1.f / 256.f);
    float inv = 1.f / sqrtf(var + 1e-5f);
    float4 gg0 = *reinterpret_cast<const float4*>(g + lane * 8);
    float4 gg1 = *reinterpret_cast<const float4*>(g + lane * 8 + 4);
    float4 bb0 = *reinterpret_cast<const float4*>(b + lane * 8);
    float4 bb1 = *reinterpret_cast<const float4*>(b + lane * 8 + 4);
    float4 o0, o1;
    o0.x = d0*inv*gg0.x + bb0.x; o0.y = d1*inv*gg0.y + bb0.y;
    o0.z = d2*inv*gg0.z + bb0.z; o0.w = d3*inv*gg0.w + bb0.w;
    o1.x = d4*inv*gg1.x + bb1.x; o1.y = d5*inv*gg1.y + bb1.y;
    o1.z = d6*inv*gg1.z + bb1.z; o1.w = d7*inv*gg1.w + bb1.w;
    float* y = Y + (size_t)row * CH + lane * 8;
    *reinterpret_cast<float4*>(y) = o0;
    *reinterpret_cast<float4*>(y + 4) = o1;
}

// ---------------- coords = h2 @ W3 + b3 + prop (warp per row) ---------------
__global__ void coords_kernel(const float* __restrict__ H2, const float* __restrict__ W3,
                              const float* __restrict__ b3, const float* __restrict__ prop,
                              float* __restrict__ out)
{
    int row = (blockIdx.x * blockDim.x + threadIdx.x) >> 5;
    if (row >= MROWS) return;
    int lane = threadIdx.x & 31;
    const float* h = H2 + (size_t)row * CH;
    float4 acc = make_float4(0.f, 0.f, 0.f, 0.f);
    for (int k = lane; k < CH; k += 32) {
        float a = h[k];
        float4 w = *reinterpret_cast<const float4*>(W3 + k * 4);
        acc.x = fmaf(a, w.x, acc.x); acc.y = fmaf(a, w.y, acc.y);
        acc.z = fmaf(a, w.z, acc.z); acc.w = fmaf(a, w.w, acc.w);
    }
#pragma unroll
    for (int off = 16; off; off >>= 1) {
        acc.x += __shfl_xor_sync(0xffffffffu, acc.x, off);
        acc.y += __shfl_xor_sync(0xffffffffu, acc.y, off);
        acc.z += __shfl_xor_sync(0xffffffffu, acc.z, off);
        acc.w += __shfl_xor_sync(0xffffffffu, acc.w, off);
    }
    if (lane == 0) {
        out[row*4+0] = acc.x + b3[0] + prop[row*4+0];
        out[row*4+1] = acc.y + b3[1] + prop[row*4+1];
        out[row*4+2] = acc.z + b3[2] + prop[row*4+2];
        out[row*4+3] = acc.w + b3[3] + prop[row*4+3];
    }
}

// ---------------- top-20 per batch (block per batch) -------------------------
__global__ void topk_kernel(const float* __restrict__ scores, float* __restrict__ scratch,
                            int* __restrict__ topIdx, float* __restrict__ topSc)
{
    int b = blockIdx.x, tid = threadIdx.x;
    const float* s = scores + b * SEQ;
    float* t = scratch + b * SEQ;
    for (int i = tid; i < SEQ; i += blockDim.x) t[i] = s[i];
    __syncthreads();
    __shared__ float rv[1024];
    __shared__ int   ri[1024];
    for (int it = 0; it < NTOP; it++) {
        float bv = -INFINITY; int bi = 0x7fffffff;
        for (int i = tid; i < SEQ; i += blockDim.x) {
            float v = t[i];
            if (v > bv) { bv = v; bi = i; }
        }
        rv[tid] = bv; ri[tid] = bi;
        __syncthreads();
        for (int off = 512; off > 0; off >>= 1) {
            if (tid < off) {
                float ov = rv[tid + off]; int oi = ri[tid + off];
                if (ov > rv[tid] || (ov == rv[tid] && oi < ri[tid])) { rv[tid] = ov; ri[tid] = oi; }
            }
            __syncthreads();
        }
        if (tid == 0) {
            topIdx[b * NTOP + it] = ri[0];
            topSc[b * NTOP + it]  = rv[0];
            t[ri[0]] = -INFINITY;
        }
        __syncthreads();
    }
}

// ---------------- final: gather + sigmoid + boxes + NMS ----------------------
__global__ void final_kernel(const float* __restrict__ logits, const float* __restrict__ coords,
                             const int* __restrict__ topIdx, const float* __restrict__ topSc,
                             const float* __restrict__ WH, float* __restrict__ out)
{
    int b = blockIdx.x, tid = threadIdx.x;
    __shared__ int   idxs[NTOP];
    __shared__ float refp[NTOP][4];
    __shared__ float boxes[NTOP][4];
    if (tid < NTOP) idxs[tid] = topIdx[b * NTOP + tid];
    __syncthreads();

    for (int o = tid; o < NTOP * NC; o += blockDim.x) {
        int k = o / NC, c = o % NC;
        size_t row = (size_t)b * SEQ + idxs[k];
        out[OFF_OUT + b * (NTOP * (NC + 4)) + k * (NC + 4) + c] = logits[row * NC + c];
    }
    if (tid < NTOP * 4) {
        int k = tid >> 2, c = tid & 3;
        size_t row = (size_t)b * SEQ + idxs[k];
        float v = coords[row * 4 + c];
        out[OFF_OUT + b * (NTOP * (NC + 4)) + k * (NC + 4) + NC + c] = v;
        float r = 1.f / (1.f + expf(-v));
        out[OFF_REF + b * (NTOP * 4) + k * 4 + c] = r;
        refp[k][c] = r;
    }
    if (tid < NTOP) out[OFF_SC + b * NTOP + tid] = topSc[b * NTOP + tid];
    __syncthreads();
    if (tid < NTOP) {
        float cx = refp[tid][0], cy = refp[tid][1], w = refp[tid][2], h = refp[tid][3];
        boxes[tid][0] = truncf((cx - 0.5f * w) * WH[b * 4 + 0]);
        boxes[tid][1] = truncf((cy - 0.5f * h) * WH[b * 4 + 1]);
        boxes[tid][2] = truncf((cx + 0.5f * w) * WH[b * 4 + 2]);
        boxes[tid][3] = truncf((cy + 0.5f * h) * WH[b * 4 + 3]);
    }
    __syncthreads();
    if (tid == 0) {
        bool supp[NTOP];
        float area[NTOP];
        for (int k = 0; k < NTOP; k++) {
            supp[k] = false;
            area[k] = (boxes[k][2] - boxes[k][0]) * (boxes[k][3] - boxes[k][1]);
        }
        for (int i = 0; i < NTOP; i++) {
            if (supp[i]) continue;
            for (int j = i + 1; j < NTOP; j++) {
                float xx1 = fmaxf(boxes[i][0], boxes[j][0]);
                float yy1 = fmaxf(boxes[i][1], boxes[j][1]);
                float xx2 = fminf(boxes[i][2], boxes[j][2]);
                float yy2 = fminf(boxes[i][3], boxes[j][3]);
                float inter = fmaxf(xx2 - xx1, 0.f) * fmaxf(yy2 - yy1, 0.f);
                float iou = inter / (area[i] + area[j] - inter);
                if (iou > 0.5f) supp[j] = true;
            }
        }
        for (int k = 0; k < NTOP; k++)
            out[OFF_KEEP + b * NTOP + k] = supp[k] ? 0.f : 1.f;
    }
}

// ---------------- launch -----------------------------------------------------
extern "C" void kernel_launch(void* const* d_in, const int* in_sizes, int n_in,
                              void* d_out, int out_size)
{
    const float* memory        = (const float*)d_in[0];
    const unsigned char* mask  = (const unsigned char*)d_in[1];
    const float* WH            = (const float*)d_in[2];
    const float* W_enc         = (const float*)d_in[3];
    const float* b_enc         = (const float*)d_in[4];
    const float* ln_g          = (const float*)d_in[5];
    const float* ln_b          = (const float*)d_in[6];
    const float* W_cls         = (const float*)d_in[7];
    const float* b_cls         = (const float*)d_in[8];
    const float* W1            = (const float*)d_in[9];
    const float* b1            = (const float*)d_in[10];
    const float* W2            = (const float*)d_in[11];
    const float* b2            = (const float*)d_in[12];
    const float* W3            = (const float*)d_in[13];
    const float* b3            = (const float*)d_in[14];
    float* out = (float*)d_out;

    float *p_tmp, *p_outmem, *p_h1, *p_logits, *p_scores, *p_scratch, *p_prop, *p_coords, *p_topsc;
    unsigned char* p_rowinv; int* p_topidx;
    cudaGetSymbolAddress((void**)&p_tmp,     g_tmp);
    cudaGetSymbolAddress((void**)&p_outmem,  g_outmem);
    cudaGetSymbolAddress((void**)&p_h1,      g_h1);
    cudaGetSymbolAddress((void**)&p_logits,  g_logits);
    cudaGetSymbolAddress((void**)&p_scores,  g_scores);
    cudaGetSymbolAddress((void**)&p_scratch, g_scratch);
    cudaGetSymbolAddress((void**)&p_prop,    g_prop);
    cudaGetSymbolAddress((void**)&p_coords,  g_coords);
    cudaGetSymbolAddress((void**)&p_rowinv,  g_rowinv);
    cudaGetSymbolAddress((void**)&p_topidx,  g_topidx);
    cudaGetSymbolAddress((void**)&p_topsc,   g_topsc);

    props_kernel<<<(MROWS + 255) / 256, 256>>>(mask, p_rowinv, p_prop);

    dim3 gFull((MROWS + 127) / 128, 2);
    dim3 gCls((MROWS + 127) / 128, 1);
    // tmp = mem_masked @ W_enc + b_enc
    sgemm2_kernel<<<gFull, 256>>>(memory, W_enc, b_enc, p_tmp, MROWS, CH, 0, p_rowinv, nullptr);
    // out_mem = LN(tmp)*g + b
    ln_kernel<<<MROWS / 8, 256>>>(p_tmp, ln_g, ln_b, p_outmem);
    // h1 = relu(out_mem @ W1 + b1)
    sgemm2_kernel<<<gFull, 256>>>(p_outmem, W1, b1, p_h1, MROWS, CH, 1, nullptr, nullptr);
    // h2 = relu(h1 @ W2 + b2)  (reuse tmp)
    sgemm2_kernel<<<gFull, 256>>>(p_h1, W2, b2, p_tmp, MROWS, CH, 1, nullptr, nullptr);
    // logits = out_mem @ W_cls + b_cls, with fused row-max -> scores
    sgemm2_kernel<<<gCls, 256>>>(p_outmem, W_cls, b_cls, p_logits, MROWS, NC, 0, nullptr, p_scores);
    // coords = h2 @ W3 + b3 + prop
    coords_kernel<<<SEQ, 256>>>(p_tmp, W3, b3, p_prop, p_coords);
    // top-20 per batch
    topk_kernel<<<BSZ, 1024>>>(p_scores, p_scratch, p_topidx, p_topsc);
    // gather + sigmoid + NMS + writes
    final_kernel<<<BSZ, 128>>>(p_logits, p_coords, p_topidx, p_topsc, WH, out);

    (void)in_sizes; (void)n_in; (void)out_size;
}